// round 17
// baseline (speedup 1.0000x reference)
#include <cuda_runtime.h>
#include <cuda_fp16.h>

// ---------------------------------------------------------------------------
// GCNRegression: 2x GCNConv(+relu) + linear head.
// N=100000, E=1.6M, F=128, H=64. edge_index arrives int32.
//
// R17 = R15 (best, 149.5us; R16's big-unroll agg regressed and is reverted)
// + ONE change: agg processes TWO edges per warp-step. Lanes 0-15 own edge j,
// lanes 16-31 edge j+1; each lane loads uint2 (4 halves) so one LDG.64
// covers two 128B rows, and pair metadata is one broadcast LDG.128.
// Halves the LDG issue count of the LSU-floor-bound agg kernels.
// ---------------------------------------------------------------------------

#define NMAX 100000
#define EMAX 1600000
#define HID 64
#define SCAN_CHUNK 4096

__device__ __align__(16) float2 g_dc[NMAX];            // {deg_sum, count}
__device__ __align__(16) float  g_dis[NMAX];
__device__ __align__(16) int    g_rowptr[NMAX + 1];
__device__ __align__(16) int    g_pos[NMAX];
__device__ __align__(16) int    g_bsum[1024];
__device__ __align__(16) int    g_boff[1024];
__device__ __align__(16) float2 g_edge[EMAX];          // {src_as_float_bits, coef}
__device__ __align__(16) __half g_bufA[(size_t)NMAX * HID];
__device__ __align__(16) __half g_bufB[(size_t)NMAX * HID];

// ---- zero {deg, cnt} -------------------------------------------------------
__global__ void k_zero_dc(int n) {
    int i = blockIdx.x * blockDim.x + threadIdx.x;
    if (i < n) g_dc[i] = make_float2(0.f, 0.f);
}

// ---- weighted in-degree + histogram, one vector RED per edge ---------------
__global__ void k_deg_hist(const int* __restrict__ dst,
                           const float* __restrict__ ew, int E) {
    int e = blockIdx.x * blockDim.x + threadIdx.x;
    if (e < E) {
        int d = dst[e];
        float w = ew[e];
        asm volatile("red.global.add.v2.f32 [%0], {%1,%2};"
                     :: "l"(&g_dc[d]), "f"(w), "f"(1.0f) : "memory");
    }
}

// ---- scan phase 1 over counts (+ fused dis = rsqrt(1+deg)) -----------------
__global__ void k_scan1(int n) {
    __shared__ int ts[1024];
    int t = threadIdx.x, b = blockIdx.x;
    int base = b * SCAN_CHUNK + t * 4;
    int c[4];
#pragma unroll
    for (int r = 0; r < 4; r++) {
        if (base + r < n) {
            float2 dc = g_dc[base + r];
            c[r] = (int)dc.y;
            g_dis[base + r] = rsqrtf(1.0f + dc.x);
        } else c[r] = 0;
    }
    int s = c[0] + c[1] + c[2] + c[3];
    ts[t] = s;
    __syncthreads();
    for (int d = 1; d < 1024; d <<= 1) {
        int v = (t >= d) ? ts[t - d] : 0;
        __syncthreads();
        ts[t] += v;
        __syncthreads();
    }
    int excl = ts[t] - s;
    if (base + 0 < n) g_rowptr[base + 0] = excl;
    if (base + 1 < n) g_rowptr[base + 1] = excl + c[0];
    if (base + 2 < n) g_rowptr[base + 2] = excl + c[0] + c[1];
    if (base + 3 < n) g_rowptr[base + 3] = excl + c[0] + c[1] + c[2];
    if (t == 1023) g_bsum[b] = ts[1023];
}

// ---- scan phase 2: scan block sums (nb <= 1024) ----------------------------
__global__ void k_scan2(int nb, int n, int E) {
    __shared__ int ts[1024];
    int t = threadIdx.x;
    int v = (t < nb) ? g_bsum[t] : 0;
    ts[t] = v;
    __syncthreads();
    for (int d = 1; d < 1024; d <<= 1) {
        int u = (t >= d) ? ts[t - d] : 0;
        __syncthreads();
        ts[t] += u;
        __syncthreads();
    }
    if (t < nb) g_boff[t] = ts[t] - v;
    if (t == 0) g_rowptr[n] = E;
}

// ---- scan phase 3: add block offsets, init cursors -------------------------
__global__ void k_scan3(int n) {
    int i = blockIdx.x * blockDim.x + threadIdx.x;
    if (i < n) {
        int r = g_rowptr[i] + g_boff[i / SCAN_CHUNK];
        g_rowptr[i] = r;
        g_pos[i] = r;
    }
}

// ---- scatter edges into dst-sorted CSR order (packed meta) -----------------
__global__ void k_scatter(const int* __restrict__ src,
                          const int* __restrict__ dst,
                          const float* __restrict__ ew, int E) {
    int e = blockIdx.x * blockDim.x + threadIdx.x;
    if (e >= E) return;
    int s = src[e];
    int d = dst[e];
    int p = atomicAdd(&g_pos[d], 1);
    g_edge[p] = make_float2(__int_as_float(s), g_dis[s] * ew[e] * g_dis[d]);
}

// ---- tensor-core GEMM: Y[n,64] = X[n,K] @ W[64,K]^T  (fp16 in, f32 acc) ----
// 256 thr = 8 warps; block tile 128 rows x 64 cols; warp = 16 rows x 64 cols
// (8 n-tiles of m16n8k16). K chunked by 64 halves. Smem rows padded to 72
// halves (144B pitch) -> fragment LDS.32s (8 rows apart) are conflict-free.
#define XPITCH 72

template <int K, bool F16IN>
__global__ __launch_bounds__(256) void k_gemm_tc(
        const void* __restrict__ Xv, const float* __restrict__ W,
        __half* __restrict__ Y, int n) {
    __shared__ __half Xs[128][XPITCH];
    __shared__ __half Wt[64][XPITCH];

    const int tid  = threadIdx.x;
    const int warp = tid >> 5;
    const int lane = tid & 31;
    const int g    = lane >> 2;
    const int tq   = lane & 3;
    const int row0 = blockIdx.x * 128;
    const int rA   = warp * 16 + g;

    float d0[8], d1[8], d2[8], d3[8];
#pragma unroll
    for (int t = 0; t < 8; t++) { d0[t] = d1[t] = d2[t] = d3[t] = 0.f; }

    for (int kc = 0; kc < K; kc += 64) {
        if (kc) __syncthreads();
        if (F16IN) {
            const uint4* X8 = (const uint4*)Xv;
#pragma unroll
            for (int i = 0; i < 4; i++) {
                int idx = tid + i * 256;
                int r = idx >> 3, q = idx & 7;
                int row = row0 + r;
                uint4 u = (row < n) ? X8[(size_t)row * (K / 8) + (kc >> 3) + q]
                                    : make_uint4(0u, 0u, 0u, 0u);
                *(uint4*)&Xs[r][q * 8] = u;
            }
        } else {
            const float4* X4 = (const float4*)Xv;
#pragma unroll
            for (int i = 0; i < 8; i++) {
                int idx = tid + i * 256;
                int r = idx >> 4, q = idx & 15;
                int row = row0 + r;
                float4 a = (row < n) ? X4[(size_t)row * (K / 4) + (kc >> 2) + q]
                                     : make_float4(0.f, 0.f, 0.f, 0.f);
                __half2 p0 = __floats2half2_rn(a.x, a.y);
                __half2 p1 = __floats2half2_rn(a.z, a.w);
                *(uint2*)&Xs[r][q * 4] = make_uint2(*(unsigned*)&p0, *(unsigned*)&p1);
            }
        }
#pragma unroll
        for (int i = 0; i < 16; i++) {
            int idx = tid + i * 256;
            int c = idx >> 6, k = idx & 63;
            Wt[c][k] = __float2half(W[(size_t)c * K + kc + k]);
        }
        __syncthreads();

#pragma unroll
        for (int ks = 0; ks < 64; ks += 16) {
            unsigned a0 = *(const unsigned*)&Xs[rA][ks + tq * 2];
            unsigned a1 = *(const unsigned*)&Xs[rA + 8][ks + tq * 2];
            unsigned a2 = *(const unsigned*)&Xs[rA][ks + tq * 2 + 8];
            unsigned a3 = *(const unsigned*)&Xs[rA + 8][ks + tq * 2 + 8];
#pragma unroll
            for (int nt = 0; nt < 8; nt++) {
                unsigned b0 = *(const unsigned*)&Wt[nt * 8 + g][ks + tq * 2];
                unsigned b1 = *(const unsigned*)&Wt[nt * 8 + g][ks + tq * 2 + 8];
                asm volatile(
                    "mma.sync.aligned.m16n8k16.row.col.f32.f16.f16.f32 "
                    "{%0,%1,%2,%3}, {%4,%5,%6,%7}, {%8,%9}, {%0,%1,%2,%3};"
                    : "+f"(d0[nt]), "+f"(d1[nt]), "+f"(d2[nt]), "+f"(d3[nt])
                    : "r"(a0), "r"(a1), "r"(a2), "r"(a3), "r"(b0), "r"(b1));
            }
        }
    }

    int rowA = row0 + warp * 16 + g;
    int rowB = rowA + 8;
#pragma unroll
    for (int nt = 0; nt < 8; nt++) {
        int col = nt * 8 + tq * 2;
        if (rowA < n) {
            __half2 p = __floats2half2_rn(d0[nt], d1[nt]);
            *(unsigned*)&Y[(size_t)rowA * HID + col] = *(unsigned*)&p;
        }
        if (rowB < n) {
            __half2 p = __floats2half2_rn(d2[nt], d3[nt]);
            *(unsigned*)&Y[(size_t)rowB * HID + col] = *(unsigned*)&p;
        }
    }
}

// ---- agg core: 2 edges per warp-step ---------------------------------------
// half = lane>>4 selects edge within a pair; sub = lane&15 selects the 4-col
// group (cols 4*sub..4*sub+3). Gathers are uint2 (4 halves) per lane: one
// LDG.64 instruction covers both edges' 128B rows. Pair meta = one broadcast
// float4. After the loop, shfl_xor(16) merges the two edge-parity partials.
__device__ __forceinline__ void acc4(float c, uint2 u,
                                     float& a0, float& a1, float& a2, float& a3) {
    float2 f0 = __half22float2(*(__half2*)&u.x);
    float2 f1 = __half22float2(*(__half2*)&u.y);
    a0 = fmaf(c, f0.x, a0); a1 = fmaf(c, f0.y, a1);
    a2 = fmaf(c, f1.x, a2); a3 = fmaf(c, f1.y, a3);
}

__device__ __forceinline__ void agg_body(const __half* __restrict__ xw,
                                         int node, int half, int sub,
                                         float& a0, float& a1,
                                         float& a2, float& a3) {
    int j   = g_rowptr[node];
    int end = g_rowptr[node + 1];
    a0 = a1 = a2 = a3 = 0.f;

    // peel a leading edge if j is odd (keeps float4 meta loads 16B-aligned)
    if ((j & 1) && j < end) {
        float2 m = __ldg(&g_edge[j]);
        int   s = __float_as_int(m.x);
        float c = half ? 0.f : m.y;
        uint2 u = __ldg((const uint2*)(xw + (size_t)s * HID) + sub);
        acc4(c, u, a0, a1, a2, a3);
        j++;
    }
    // pairs, unrolled x2 (4 edges in flight)
    for (; j + 3 < end; j += 4) {
        float4 mA = __ldg((const float4*)&g_edge[j]);
        float4 mB = __ldg((const float4*)&g_edge[j + 2]);
        int   sA = __float_as_int(half ? mA.z : mA.x);
        float cA = half ? mA.w : mA.y;
        int   sB = __float_as_int(half ? mB.z : mB.x);
        float cB = half ? mB.w : mB.y;
        uint2 uA = __ldg((const uint2*)(xw + (size_t)sA * HID) + sub);
        uint2 uB = __ldg((const uint2*)(xw + (size_t)sB * HID) + sub);
        acc4(cA, uA, a0, a1, a2, a3);
        acc4(cB, uB, a0, a1, a2, a3);
    }
    if (j + 1 < end) {
        float4 m = __ldg((const float4*)&g_edge[j]);
        int   s = __float_as_int(half ? m.z : m.x);
        float c = half ? m.w : m.y;
        uint2 u = __ldg((const uint2*)(xw + (size_t)s * HID) + sub);
        acc4(c, u, a0, a1, a2, a3);
        j += 2;
    }
    if (j < end) {
        float2 m = __ldg(&g_edge[j]);
        int   s = __float_as_int(m.x);
        float c = half ? 0.f : m.y;
        uint2 u = __ldg((const uint2*)(xw + (size_t)s * HID) + sub);
        acc4(c, u, a0, a1, a2, a3);
    }
    // merge the two edge-parity halves: both halves end with full sums
    a0 += __shfl_xor_sync(0xffffffffu, a0, 16);
    a1 += __shfl_xor_sync(0xffffffffu, a1, 16);
    a2 += __shfl_xor_sync(0xffffffffu, a2, 16);
    a3 += __shfl_xor_sync(0xffffffffu, a3, 16);
}

// ---- layer aggregation + self-loop + bias + relu (1 warp/node) -------------
__global__ void k_agg_relu(const __half* __restrict__ xw,
                           const float* __restrict__ b,
                           __half* __restrict__ out, int n) {
    int node = (blockIdx.x * blockDim.x + threadIdx.x) >> 5;
    int lane = threadIdx.x & 31;
    if (node >= n) return;
    int half = lane >> 4, sub = lane & 15;
    float a0, a1, a2, a3;
    agg_body(xw, node, half, sub, a0, a1, a2, a3);
    float ds = g_dis[node];
    float d2 = ds * ds;
    uint2 xu = __ldg((const uint2*)(xw + (size_t)node * HID) + sub);
    float2 x0 = __half22float2(*(__half2*)&xu.x);
    float2 x1 = __half22float2(*(__half2*)&xu.y);
    float4 bb = __ldg((const float4*)b + sub);
    float r0 = fmaxf(fmaf(d2, x0.x, a0) + bb.x, 0.f);
    float r1 = fmaxf(fmaf(d2, x0.y, a1) + bb.y, 0.f);
    float r2 = fmaxf(fmaf(d2, x1.x, a2) + bb.z, 0.f);
    float r3 = fmaxf(fmaf(d2, x1.y, a3) + bb.w, 0.f);
    if (half == 0) {
        __half2 p0 = __floats2half2_rn(r0, r1);
        __half2 p1 = __floats2half2_rn(r2, r3);
        ((uint2*)(out + (size_t)node * HID))[sub] =
            make_uint2(*(unsigned*)&p0, *(unsigned*)&p1);
    }
}

// ---- final aggregation + relu + head dot W3 (1 warp/node) ------------------
__global__ void k_agg_head(const __half* __restrict__ xw,
                           const float* __restrict__ b2,
                           const float* __restrict__ W3,
                           const float* __restrict__ b3,
                           float* __restrict__ out, int n) {
    int node = (blockIdx.x * blockDim.x + threadIdx.x) >> 5;
    int lane = threadIdx.x & 31;
    if (node >= n) return;
    int half = lane >> 4, sub = lane & 15;
    float a0, a1, a2, a3;
    agg_body(xw, node, half, sub, a0, a1, a2, a3);
    float ds = g_dis[node];
    float d2 = ds * ds;
    uint2 xu = __ldg((const uint2*)(xw + (size_t)node * HID) + sub);
    float2 x0 = __half22float2(*(__half2*)&xu.x);
    float2 x1 = __half22float2(*(__half2*)&xu.y);
    float4 bb = __ldg((const float4*)b2 + sub);
    float h0 = fmaxf(fmaf(d2, x0.x, a0) + bb.x, 0.f);
    float h1 = fmaxf(fmaf(d2, x0.y, a1) + bb.y, 0.f);
    float h2 = fmaxf(fmaf(d2, x1.x, a2) + bb.z, 0.f);
    float h3 = fmaxf(fmaf(d2, x1.y, a3) + bb.w, 0.f);
    float4 w = __ldg((const float4*)W3 + sub);
    float sum = fmaf(h0, w.x, fmaf(h1, w.y, fmaf(h2, w.z, h3 * w.w)));
#pragma unroll
    for (int off = 8; off; off >>= 1)
        sum += __shfl_xor_sync(0xffffffffu, sum, off);
    if (lane == 0) out[node] = sum + b3[0];
}

extern "C" void kernel_launch(void* const* d_in, const int* in_sizes, int n_in,
                              void* d_out, int out_size) {
    const float* x   = (const float*)d_in[0];
    const int*   ei  = (const int*)d_in[1];       // int32 (JAX x64 disabled)
    const float* ew  = (const float*)d_in[2];
    // d_in[3] = batch (unused)
    const float* W1  = (const float*)d_in[4];
    const float* b1  = (const float*)d_in[5];
    const float* W2  = (const float*)d_in[6];
    const float* b2  = (const float*)d_in[7];
    const float* W3  = (const float*)d_in[8];
    const float* b3  = (const float*)d_in[9];
    float*       out = (float*)d_out;

    const int n = in_sizes[0] / 128;   // 100000
    const int E = in_sizes[1] / 2;     // 1600000
    const int* src = ei;
    const int* dst = ei + E;

    __half *dA, *dB;
    cudaGetSymbolAddress((void**)&dA, g_bufA);
    cudaGetSymbolAddress((void**)&dB, g_bufB);

    const int TB = 256;
    const int NB = (n + SCAN_CHUNK - 1) / SCAN_CHUNK;
    const int GB = (n + 127) / 128;

    // fork: CSR chain on s2, gemm128 on stream 0
    cudaStream_t s2;
    cudaEvent_t evA, evB;
    cudaStreamCreateWithFlags(&s2, cudaStreamNonBlocking);
    cudaEventCreateWithFlags(&evA, cudaEventDisableTiming);
    cudaEventCreateWithFlags(&evB, cudaEventDisableTiming);

    cudaEventRecord(evA, 0);
    cudaStreamWaitEvent(s2, evA, 0);

    // -- CSR chain (s2)
    k_zero_dc<<<(n + TB - 1) / TB, TB, 0, s2>>>(n);
    k_deg_hist<<<(E + TB - 1) / TB, TB, 0, s2>>>(dst, ew, E);
    k_scan1<<<NB, 1024, 0, s2>>>(n);
    k_scan2<<<1, 1024, 0, s2>>>(NB, n, E);
    k_scan3<<<(n + TB - 1) / TB, TB, 0, s2>>>(n);
    k_scatter<<<(E + TB - 1) / TB, TB, 0, s2>>>(src, dst, ew, E);
    cudaEventRecord(evB, s2);

    // -- stream 0: xw1 = x @ W1^T (tensor cores, fp16 out)
    k_gemm_tc<128, false><<<GB, TB>>>(x, W1, dA, n);

    // join, then serial tail
    cudaStreamWaitEvent(0, evB, 0);
    k_agg_relu<<<(n * 32 + TB - 1) / TB, TB>>>(dA, b1, dB, n);
    k_gemm_tc<64, true><<<GB, TB>>>(dB, W2, dA, n);
    k_agg_head<<<(n * 32 + TB - 1) / TB, TB>>>(dA, b2, W3, b3, out, n);
}